// round 2
// baseline (speedup 1.0000x reference)
#include <cuda_runtime.h>
#include <cuda_bf16.h>
#include <math.h>

// Problem constants (fixed by the reference):
//   T=256 timesteps, B=256 batch, IN=512 input, H=512 hidden
#define TT  256
#define BB  256
#define IND 512
#define HH  512
#define G4  (4*HH)          // 2048 gate columns
#define BH  (BB*HH)         // 131072 state elements
#define MROWS (TT*BB)       // 65536 rows for the input GEMM

// -------- persistent device scratch (no cudaMalloc allowed) --------
__device__ float g_xgates[(size_t)MROWS * G4];   // 512 MB: x @ W_ih^T + b, all timesteps
__device__ float g_gates [(size_t)BB * G4];      // 2 MB : per-step gate buffer
__device__ float g_h     [BH];                   // hidden state (already done-masked)
__device__ float g_c     [BH];                   // cell state   (already done-masked)

// ---------------------------------------------------------------
// Generic NT SGEMM: C[M,N] = A[M,K] * B[N,K]^T (+ Cadd) (+ bias0 + bias1)
// A, B row-major with contiguous K. Sizes must divide the tile sizes.
// ---------------------------------------------------------------
template<int BM, int BN, int BK, int TM, int TN>
__global__ void sgemm_nt_kernel(int M, int N, int K,
                                const float* __restrict__ A,
                                const float* __restrict__ B,
                                const float* __restrict__ Cadd,   // [M,N] or null
                                const float* __restrict__ bias0,  // [N] or null
                                const float* __restrict__ bias1,  // [N] or null
                                float* __restrict__ C)
{
    constexpr int THREADS = (BM / TM) * (BN / TN);
    __shared__ float As[BK][BM + 4];
    __shared__ float Bs[BK][BN + 4];

    const int tid = threadIdx.x;
    const int block_m = blockIdx.y * BM;
    const int block_n = blockIdx.x * BN;

    const int tcol = tid % (BN / TN);   // tile column of this thread
    const int trow = tid / (BN / TN);   // tile row

    float acc[TM][TN];
#pragma unroll
    for (int i = 0; i < TM; i++)
#pragma unroll
        for (int j = 0; j < TN; j++) acc[i][j] = 0.f;

    constexpr int A_LD = (BM * BK) / (THREADS * 4);  // float4 loads per thread
    constexpr int B_LD = (BN * BK) / (THREADS * 4);

    for (int k0 = 0; k0 < K; k0 += BK) {
#pragma unroll
        for (int i = 0; i < A_LD; i++) {
            int lin = (tid + i * THREADS) * 4;   // element index in [BM x BK] tile
            int m = lin / BK, kk = lin % BK;
            float4 v = *reinterpret_cast<const float4*>(&A[(size_t)(block_m + m) * K + k0 + kk]);
            As[kk + 0][m] = v.x; As[kk + 1][m] = v.y;
            As[kk + 2][m] = v.z; As[kk + 3][m] = v.w;
        }
#pragma unroll
        for (int i = 0; i < B_LD; i++) {
            int lin = (tid + i * THREADS) * 4;
            int n = lin / BK, kk = lin % BK;
            float4 v = *reinterpret_cast<const float4*>(&B[(size_t)(block_n + n) * K + k0 + kk]);
            Bs[kk + 0][n] = v.x; Bs[kk + 1][n] = v.y;
            Bs[kk + 2][n] = v.z; Bs[kk + 3][n] = v.w;
        }
        __syncthreads();

#pragma unroll
        for (int kk = 0; kk < BK; kk++) {
            float a[TM], b[TN];
#pragma unroll
            for (int i = 0; i < TM; i += 4) {
                float4 v = *reinterpret_cast<const float4*>(&As[kk][trow * TM + i]);
                a[i] = v.x; a[i+1] = v.y; a[i+2] = v.z; a[i+3] = v.w;
            }
#pragma unroll
            for (int j = 0; j < TN; j += 4) {
                float4 v = *reinterpret_cast<const float4*>(&Bs[kk][tcol * TN + j]);
                b[j] = v.x; b[j+1] = v.y; b[j+2] = v.z; b[j+3] = v.w;
            }
#pragma unroll
            for (int i = 0; i < TM; i++)
#pragma unroll
                for (int j = 0; j < TN; j++)
                    acc[i][j] = fmaf(a[i], b[j], acc[i][j]);
        }
        __syncthreads();
    }

    // epilogue
#pragma unroll
    for (int i = 0; i < TM; i++) {
        int m = block_m + trow * TM + i;
#pragma unroll
        for (int j = 0; j < TN; j++) {
            int n = block_n + tcol * TN + j;
            float v = acc[i][j];
            if (Cadd)  v += Cadd[(size_t)m * N + n];
            if (bias0) v += bias0[n];
            if (bias1) v += bias1[n];
            C[(size_t)m * N + n] = v;
        }
    }
}

// ---------------------------------------------------------------
// init: zero h, c and hidden_out[t=0] (state starts at 0, so the masked
// pre-step state at t=0 is 0 regardless of dones[0]).
// ---------------------------------------------------------------
__global__ void init_kernel(float* __restrict__ hidden_out)
{
    int idx = blockIdx.x * blockDim.x + threadIdx.x;   // 0 .. 2*BH-1
    if (idx < BH) { g_h[idx] = 0.f; g_c[idx] = 0.f; }
    hidden_out[idx] = 0.f;                              // [0, 2*BH): h then c at t=0
}

__device__ __forceinline__ float sigf(float x) { return 1.f / (1.f + expf(-x)); }

// ---------------------------------------------------------------
// update: LSTM pointwise for step t, then apply dones[t+1] mask and store
// hidden_out[t+1] (the "pre" state of the next step).
// ---------------------------------------------------------------
__global__ void update_kernel(int t,
                              const int* __restrict__ dones,
                              float* __restrict__ lstm_out,
                              float* __restrict__ hidden_out)
{
    int idx = blockIdx.x * blockDim.x + threadIdx.x;   // 0 .. BH-1
    int b = idx >> 9;          // / H
    int j = idx & (HH - 1);    // % H

    const float* gr = g_gates + (size_t)b * G4;
    float ig = gr[j];
    float fg = gr[j + HH];
    float gg = gr[j + 2 * HH];
    float og = gr[j + 3 * HH];

    float c  = g_c[idx];
    float cn = sigf(fg) * c + sigf(ig) * tanhf(gg);
    float hn = sigf(og) * tanhf(cn);

    lstm_out[(size_t)t * BH + idx] = hn;

    if (t + 1 < TT) {
        float keep = 1.f - (float)dones[(t + 1) * BB + b];
        hn *= keep;
        cn *= keep;
        hidden_out[(size_t)(t + 1) * 2 * BH + idx]      = hn;  // h part
        hidden_out[(size_t)(t + 1) * 2 * BH + BH + idx] = cn;  // c part
    }
    g_h[idx] = hn;
    g_c[idx] = cn;
}

// ---------------------------------------------------------------
extern "C" void kernel_launch(void* const* d_in, const int* in_sizes, int n_in,
                              void* d_out, int out_size)
{
    const float* x     = (const float*)d_in[0];   // [T,B,IN]
    const int*   dones = (const int*)  d_in[1];   // [T,B]
    const float* W_ih  = (const float*)d_in[2];   // [4H,IN]
    const float* W_hh  = (const float*)d_in[3];   // [4H,H]
    const float* b_ih  = (const float*)d_in[4];   // [4H]
    const float* b_hh  = (const float*)d_in[5];   // [4H]

    float* out        = (float*)d_out;
    float* lstm_out   = out;                       // [T,B,H]
    float* hidden_out = out + (size_t)TT * BH;     // [T,2,B,H]

    float *p_xgates, *p_gates, *p_h;
    cudaGetSymbolAddress((void**)&p_xgates, g_xgates);
    cudaGetSymbolAddress((void**)&p_gates,  g_gates);
    cudaGetSymbolAddress((void**)&p_h,      g_h);

    // 1) zero state + hidden_out[0]
    init_kernel<<<(2 * BH) / 256, 256>>>(hidden_out);

    // 2) time-parallel input GEMM: xgates = x @ W_ih^T + (b_ih + b_hh)
    {
        dim3 grid(G4 / 128, MROWS / 128);
        sgemm_nt_kernel<128, 128, 16, 8, 8><<<grid, 256>>>(
            MROWS, G4, IND, x, W_ih, nullptr, b_ih, b_hh, p_xgates);
    }

    // 3) sequential recurrence
    for (int t = 0; t < TT; t++) {
        // gates = xgates[t] + h @ W_hh^T   (h already masked by previous update)
        dim3 grid(G4 / 64, BB / 64);
        sgemm_nt_kernel<64, 64, 16, 4, 4><<<grid, 256>>>(
            BB, G4, HH, p_h, W_hh,
            p_xgates + (size_t)t * BB * G4, nullptr, nullptr, p_gates);

        update_kernel<<<BH / 256, 256>>>(t, dones, lstm_out, hidden_out);
    }
}

// round 6
// speedup vs baseline: 2.2780x; 2.2780x over previous
#include <cuda_runtime.h>
#include <cuda_bf16.h>
#include <math.h>
#include <mma.h>
using namespace nvcuda;

// Problem constants: T=256, B=256, IN=512, H=512
#define TT  256
#define BB  256
#define IND 512
#define HH  512
#define G4  (4*HH)          // 2048 gate columns
#define BH  (BB*HH)         // 131072 state elements
#define MROWS (TT*BB)       // 65536 rows for the input GEMM

// -------- persistent device scratch (no cudaMalloc allowed) --------
__device__ float g_xgates[(size_t)MROWS * G4];            // 512 MB
__device__ __nv_bfloat16 g_Wih_hi[(size_t)G4 * IND];      // gate-interleaved splits
__device__ __nv_bfloat16 g_Wih_lo[(size_t)G4 * IND];
__device__ __nv_bfloat16 g_Whh_hi[(size_t)G4 * HH];
__device__ __nv_bfloat16 g_Whh_lo[(size_t)G4 * HH];
__device__ float g_b2[G4];                                // merged bias
__device__ float g_h[BH];                                 // hidden (masked)
__device__ float g_c[BH];                                 // cell   (masked)

__device__ __forceinline__ float sigf(float x) { return 1.f / (1.f + expf(-x)); }

__device__ __forceinline__ void split_bf16(float v, __nv_bfloat16& hi, __nv_bfloat16& lo) {
    hi = __float2bfloat16(v);
    lo = __float2bfloat16(v - __bfloat162float(hi));
}

// ---------------------------------------------------------------
// Reorder weights gate-interleaved (new row 4j+p <- old row p*H+j)
// and split into bf16 hi/lo. Also merge biases.
// ---------------------------------------------------------------
__global__ void reorder_kernel(const float* __restrict__ Wih,
                               const float* __restrict__ Whh,
                               const float* __restrict__ bih,
                               const float* __restrict__ bhh)
{
    int idx = blockIdx.x * blockDim.x + threadIdx.x;  // over G4*512
    int row = idx >> 9;
    int k   = idx & 511;
    int j = row >> 2, p = row & 3;
    int src = p * HH + j;

    __nv_bfloat16 hi, lo;
    split_bf16(Wih[(size_t)src * IND + k], hi, lo);
    g_Wih_hi[idx] = hi; g_Wih_lo[idx] = lo;
    split_bf16(Whh[(size_t)src * HH + k], hi, lo);
    g_Whh_hi[idx] = hi; g_Whh_lo[idx] = lo;

    if (idx < G4) {
        int jj = idx >> 2, pp = idx & 3;
        int s = pp * HH + jj;
        g_b2[idx] = bih[s] + bhh[s];
    }
}

__global__ void init_kernel(float* __restrict__ hidden_out)
{
    int idx = blockIdx.x * blockDim.x + threadIdx.x;   // 0 .. 2*BH-1
    if (idx < BH) { g_h[idx] = 0.f; g_c[idx] = 0.f; }
    hidden_out[idx] = 0.f;   // hidden_out[t=0]
}

// smem strides (bf16 elements); 40*2B = 80B, multiple of 16B for wmma ldm
#define SPAD 40

// ---------------------------------------------------------------
// Input GEMM (split-bf16 x3): xgates = x @ Wih'^T + b'
// BM=128, BN=64, BK=32; 8 warps (4x2), warp tile 32x32.
// smem: tiles (2*128 + 2*64)*SPAD*2 = 30720 B; Cs epilogue 128*64*4 = 32768 B.
// ---------------------------------------------------------------
#define XG_SMEM 32768
__global__ __launch_bounds__(256) void xgemm_kernel(const float* __restrict__ A)
{
    __shared__ __align__(16) char smem_raw[XG_SMEM];
    __nv_bfloat16* As_hi = (__nv_bfloat16*)smem_raw;                 // [128][40]
    __nv_bfloat16* As_lo = As_hi + 128 * SPAD;
    __nv_bfloat16* Bs_hi = As_lo + 128 * SPAD;                       // [64][40]
    __nv_bfloat16* Bs_lo = Bs_hi + 64 * SPAD;

    const int tid  = threadIdx.x;
    const int warp = tid >> 5;
    const int wr = warp >> 1, wc = warp & 1;       // 4x2 warp grid
    const int m0 = blockIdx.y * 128;
    const int n0 = blockIdx.x * 64;

    wmma::fragment<wmma::accumulator, 16, 16, 16, float> acc[2][2];
#pragma unroll
    for (int i = 0; i < 2; i++)
#pragma unroll
        for (int j = 0; j < 2; j++) wmma::fill_fragment(acc[i][j], 0.f);

    for (int k0 = 0; k0 < IND; k0 += 32) {
        // A tile: 128x32 fp32 -> split bf16. 1024 float4, 4 per thread.
#pragma unroll
        for (int i = 0; i < 4; i++) {
            int g = tid + i * 256;
            int m = g >> 3, kk = (g & 7) << 2;
            float4 v = *reinterpret_cast<const float4*>(&A[(size_t)(m0 + m) * IND + k0 + kk]);
            __nv_bfloat16 h0,l0,h1,l1,h2,l2,h3,l3;
            split_bf16(v.x,h0,l0); split_bf16(v.y,h1,l1);
            split_bf16(v.z,h2,l2); split_bf16(v.w,h3,l3);
            __nv_bfloat162* dh = (__nv_bfloat162*)&As_hi[m * SPAD + kk];
            __nv_bfloat162* dl = (__nv_bfloat162*)&As_lo[m * SPAD + kk];
            dh[0] = __nv_bfloat162(h0,h1); dh[1] = __nv_bfloat162(h2,h3);
            dl[0] = __nv_bfloat162(l0,l1); dl[1] = __nv_bfloat162(l2,l3);
        }
        // B tile: 64x32 bf16 (pre-split). 256 uint4 per matrix, 1 per thread.
        {
            int n = tid >> 2, kk = (tid & 3) << 3;
            *reinterpret_cast<uint4*>(&Bs_hi[n * SPAD + kk]) =
                *reinterpret_cast<const uint4*>(&g_Wih_hi[(size_t)(n0 + n) * IND + k0 + kk]);
            *reinterpret_cast<uint4*>(&Bs_lo[n * SPAD + kk]) =
                *reinterpret_cast<const uint4*>(&g_Wih_lo[(size_t)(n0 + n) * IND + k0 + kk]);
        }
        __syncthreads();

#pragma unroll
        for (int ks = 0; ks < 32; ks += 16) {
            wmma::fragment<wmma::matrix_a, 16, 16, 16, __nv_bfloat16, wmma::row_major> ah[2], al[2];
            wmma::fragment<wmma::matrix_b, 16, 16, 16, __nv_bfloat16, wmma::col_major> bh[2], bl[2];
#pragma unroll
            for (int i = 0; i < 2; i++) {
                wmma::load_matrix_sync(ah[i], &As_hi[(wr * 32 + i * 16) * SPAD + ks], SPAD);
                wmma::load_matrix_sync(al[i], &As_lo[(wr * 32 + i * 16) * SPAD + ks], SPAD);
            }
#pragma unroll
            for (int j = 0; j < 2; j++) {
                wmma::load_matrix_sync(bh[j], &Bs_hi[(wc * 32 + j * 16) * SPAD + ks], SPAD);
                wmma::load_matrix_sync(bl[j], &Bs_lo[(wc * 32 + j * 16) * SPAD + ks], SPAD);
            }
#pragma unroll
            for (int i = 0; i < 2; i++)
#pragma unroll
                for (int j = 0; j < 2; j++) {
                    wmma::mma_sync(acc[i][j], ah[i], bh[j], acc[i][j]);
                    wmma::mma_sync(acc[i][j], ah[i], bl[j], acc[i][j]);
                    wmma::mma_sync(acc[i][j], al[i], bh[j], acc[i][j]);
                }
        }
        __syncthreads();
    }

    // epilogue via smem Cs[128][64], add bias, write out
    float* Cs = (float*)smem_raw;
#pragma unroll
    for (int i = 0; i < 2; i++)
#pragma unroll
        for (int j = 0; j < 2; j++)
            wmma::store_matrix_sync(&Cs[(wr * 32 + i * 16) * 64 + wc * 32 + j * 16],
                                    acc[i][j], 64, wmma::mem_row_major);
    __syncthreads();
#pragma unroll
    for (int i = 0; i < 8; i++) {
        int g = tid + i * 256;
        int r = g >> 4, c = (g & 15) << 2;
        float4 v = *reinterpret_cast<float4*>(&Cs[r * 64 + c]);
        v.x += g_b2[n0 + c + 0]; v.y += g_b2[n0 + c + 1];
        v.z += g_b2[n0 + c + 2]; v.w += g_b2[n0 + c + 3];
        *reinterpret_cast<float4*>(&g_xgates[(size_t)(m0 + r) * G4 + n0 + c]) = v;
    }
}

// ---------------------------------------------------------------
// Fused recurrent step (split-bf16 x3 GEMM + LSTM epilogue)
// BM=64, BN=64, BK=32; 4 warps (2x2), warp tile 32x32.
// smem: tiles 4*64*SPAD*2 = 20480 B  >  Cs 64*64*4 = 16384 B  -> 20480.
// ---------------------------------------------------------------
#define ST_SMEM 20480
__global__ __launch_bounds__(128) void step_kernel(int t,
                                                   const int* __restrict__ dones,
                                                   float* __restrict__ lstm_out,
                                                   float* __restrict__ hidden_out)
{
    __shared__ __align__(16) char smem_raw[ST_SMEM];
    __nv_bfloat16* As_hi = (__nv_bfloat16*)smem_raw;       // [64][40]
    __nv_bfloat16* As_lo = As_hi + 64 * SPAD;
    __nv_bfloat16* Bs_hi = As_lo + 64 * SPAD;
    __nv_bfloat16* Bs_lo = Bs_hi + 64 * SPAD;

    const int tid  = threadIdx.x;
    const int warp = tid >> 5;
    const int wr = warp >> 1, wc = warp & 1;       // 2x2 warp grid
    const int m0 = blockIdx.y * 64;                // batch tile
    const int n0 = blockIdx.x * 64;                // gate-col tile (16 units)

    wmma::fragment<wmma::accumulator, 16, 16, 16, float> acc[2][2];
#pragma unroll
    for (int i = 0; i < 2; i++)
#pragma unroll
        for (int j = 0; j < 2; j++) wmma::fill_fragment(acc[i][j], 0.f);

    for (int k0 = 0; k0 < HH; k0 += 32) {
        // A tile: 64x32 fp32 from g_h -> split. 512 float4, 4 per thread.
#pragma unroll
        for (int i = 0; i < 4; i++) {
            int g = tid + i * 128;
            int m = g >> 3, kk = (g & 7) << 2;
            float4 v = *reinterpret_cast<const float4*>(&g_h[(size_t)(m0 + m) * HH + k0 + kk]);
            __nv_bfloat16 h0,l0,h1,l1,h2,l2,h3,l3;
            split_bf16(v.x,h0,l0); split_bf16(v.y,h1,l1);
            split_bf16(v.z,h2,l2); split_bf16(v.w,h3,l3);
            __nv_bfloat162* dh = (__nv_bfloat162*)&As_hi[m * SPAD + kk];
            __nv_bfloat162* dl = (__nv_bfloat162*)&As_lo[m * SPAD + kk];
            dh[0] = __nv_bfloat162(h0,h1); dh[1] = __nv_bfloat162(h2,h3);
            dl[0] = __nv_bfloat162(l0,l1); dl[1] = __nv_bfloat162(l2,l3);
        }
        // B tile: 64x32 pre-split bf16. 256 uint4 per matrix, 2 per thread.
#pragma unroll
        for (int i = 0; i < 2; i++) {
            int g = tid + i * 128;
            int n = g >> 2, kk = (g & 3) << 3;
            *reinterpret_cast<uint4*>(&Bs_hi[n * SPAD + kk]) =
                *reinterpret_cast<const uint4*>(&g_Whh_hi[(size_t)(n0 + n) * HH + k0 + kk]);
            *reinterpret_cast<uint4*>(&Bs_lo[n * SPAD + kk]) =
                *reinterpret_cast<const uint4*>(&g_Whh_lo[(size_t)(n0 + n) * HH + k0 + kk]);
        }
        __syncthreads();

#pragma unroll
        for (int ks = 0; ks < 32; ks += 16) {
            wmma::fragment<wmma::matrix_a, 16, 16, 16, __nv_bfloat16, wmma::row_major> ah[2], al[2];
            wmma::fragment<wmma::matrix_b, 16, 16, 16, __nv_bfloat16, wmma::col_major> bh[2], bl[2];
#pragma unroll
            for (int i = 0; i < 2; i++) {
                wmma::load_matrix_sync(ah[i], &As_hi[(wr * 32 + i * 16) * SPAD + ks], SPAD);
                wmma::load_matrix_sync(al[i], &As_lo[(wr * 32 + i * 16) * SPAD + ks], SPAD);
            }
#pragma unroll
            for (int j = 0; j < 2; j++) {
                wmma::load_matrix_sync(bh[j], &Bs_hi[(wc * 32 + j * 16) * SPAD + ks], SPAD);
                wmma::load_matrix_sync(bl[j], &Bs_lo[(wc * 32 + j * 16) * SPAD + ks], SPAD);
            }
#pragma unroll
            for (int i = 0; i < 2; i++)
#pragma unroll
                for (int j = 0; j < 2; j++) {
                    wmma::mma_sync(acc[i][j], ah[i], bh[j], acc[i][j]);
                    wmma::mma_sync(acc[i][j], ah[i], bl[j], acc[i][j]);
                    wmma::mma_sync(acc[i][j], al[i], bh[j], acc[i][j]);
                }
        }
        __syncthreads();
    }

    // stash recurrent contribution
    float* Cs = (float*)smem_raw;
#pragma unroll
    for (int i = 0; i < 2; i++)
#pragma unroll
        for (int j = 0; j < 2; j++)
            wmma::store_matrix_sync(&Cs[(wr * 32 + i * 16) * 64 + wc * 32 + j * 16],
                                    acc[i][j], 64, wmma::mem_row_major);
    __syncthreads();

    // LSTM pointwise: 64 batches x 16 units = 1024 elems, 8 per thread
#pragma unroll
    for (int e = 0; e < 8; e++) {
        int p = tid + e * 128;
        int bl = p >> 4;                 // local batch
        int u  = p & 15;                 // local unit
        int b  = m0 + bl;
        int j  = (n0 >> 2) + u;

        float4 rec = *reinterpret_cast<float4*>(&Cs[bl * 64 + (u << 2)]);
        float4 xg  = *reinterpret_cast<const float4*>(
            &g_xgates[((size_t)t * BB + b) * G4 + n0 + (u << 2)]);

        float ig = rec.x + xg.x;
        float fg = rec.y + xg.y;
        float gg = rec.z + xg.z;
        float og = rec.w + xg.w;

        int sidx = b * HH + j;
        float c  = g_c[sidx];
        float cn = sigf(fg) * c + sigf(ig) * tanhf(gg);
        float hn = sigf(og) * tanhf(cn);

        lstm_out[(size_t)t * BH + sidx] = hn;

        if (t + 1 < TT) {
            float keep = 1.f - (float)dones[(t + 1) * BB + b];
            hn *= keep;
            cn *= keep;
            hidden_out[(size_t)(t + 1) * 2 * BH + sidx]      = hn;
            hidden_out[(size_t)(t + 1) * 2 * BH + BH + sidx] = cn;
        }
        g_h[sidx] = hn;
        g_c[sidx] = cn;
    }
}

// ---------------------------------------------------------------
extern "C" void kernel_launch(void* const* d_in, const int* in_sizes, int n_in,
                              void* d_out, int out_size)
{
    const float* x     = (const float*)d_in[0];   // [T,B,IN]
    const int*   dones = (const int*)  d_in[1];   // [T,B]
    const float* W_ih  = (const float*)d_in[2];   // [4H,IN]
    const float* W_hh  = (const float*)d_in[3];   // [4H,H]
    const float* b_ih  = (const float*)d_in[4];   // [4H]
    const float* b_hh  = (const float*)d_in[5];   // [4H]

    float* out        = (float*)d_out;
    float* lstm_out   = out;                       // [T,B,H]
    float* hidden_out = out + (size_t)TT * BH;     // [T,2,B,H]

    // 0) weight reorder + bf16 split + bias merge
    reorder_kernel<<<(G4 * IND) / 256, 256>>>(W_ih, W_hh, b_ih, b_hh);

    // 1) zero state + hidden_out[0]
    init_kernel<<<(2 * BH) / 256, 256>>>(hidden_out);

    // 2) time-parallel input GEMM (bf16x3 tensor cores)
    {
        dim3 grid(G4 / 64, MROWS / 128);
        xgemm_kernel<<<grid, 256>>>(x);
    }

    // 3) fused recurrent steps
    for (int t = 0; t < TT; t++) {
        dim3 grid(G4 / 64, BB / 64);
        step_kernel<<<grid, 128>>>(t, dones, lstm_out, hidden_out);
    }
}

// round 10
// speedup vs baseline: 3.2991x; 1.4482x over previous
#include <cuda_runtime.h>
#include <cuda_bf16.h>
#include <cstdint>
#include <math.h>
#include <mma.h>
using namespace nvcuda;

// Problem constants: T=256, B=256, IN=512, H=512
#define TT  256
#define BB  256
#define IND 512
#define HH  512
#define G4  (4*HH)          // 2048 gate columns
#define BH  (BB*HH)         // 131072 state elements
#define MROWS (TT*BB)       // 65536 rows for the input GEMM

// -------- persistent device scratch (no cudaMalloc allowed) --------
__device__ float g_xgates[(size_t)MROWS * G4];            // 512 MB
__device__ __nv_bfloat16 g_Wih_hi[(size_t)G4 * IND];      // gate-interleaved splits
__device__ __nv_bfloat16 g_Wih_lo[(size_t)G4 * IND];
__device__ __nv_bfloat16 g_Whh_hi[(size_t)G4 * HH];
__device__ __nv_bfloat16 g_Whh_lo[(size_t)G4 * HH];
__device__ float g_b2[G4];                                // merged bias
__device__ __nv_bfloat16 g_hb_hi[2][BH];                  // h ping-pong, pre-split
__device__ __nv_bfloat16 g_hb_lo[2][BH];
__device__ volatile unsigned g_bar_cnt[4];                // per-m-group barrier
__device__ volatile unsigned g_bar_gen[4];

__device__ __forceinline__ float sigf(float x) { return 1.f / (1.f + expf(-x)); }

__device__ __forceinline__ void split_bf16(float v, __nv_bfloat16& hi, __nv_bfloat16& lo) {
    hi = __float2bfloat16(v);
    lo = __float2bfloat16(v - __bfloat162float(hi));
}

__device__ __forceinline__ void cp16(void* dst_smem, const void* src) {
    unsigned int d = (unsigned int)__cvta_generic_to_shared(dst_smem);
    asm volatile("cp.async.cg.shared.global [%0], [%1], 16;" :: "r"(d), "l"(src));
}
#define CP_COMMIT()  asm volatile("cp.async.commit_group;")
#define CP_WAIT(N)   asm volatile("cp.async.wait_group %0;" :: "n"(N))

// ---------------------------------------------------------------
// Reorder weights gate-interleaved (new row 4j+p <- old row p*H+j),
// split into bf16 hi/lo, merge biases.
// ---------------------------------------------------------------
__global__ void reorder_kernel(const float* __restrict__ Wih,
                               const float* __restrict__ Whh,
                               const float* __restrict__ bih,
                               const float* __restrict__ bhh)
{
    int idx = blockIdx.x * blockDim.x + threadIdx.x;  // over G4*512
    int row = idx >> 9;
    int k   = idx & 511;
    int j = row >> 2, p = row & 3;
    int src = p * HH + j;

    __nv_bfloat16 hi, lo;
    split_bf16(Wih[(size_t)src * IND + k], hi, lo);
    g_Wih_hi[idx] = hi; g_Wih_lo[idx] = lo;
    split_bf16(Whh[(size_t)src * HH + k], hi, lo);
    g_Whh_hi[idx] = hi; g_Whh_lo[idx] = lo;

    if (idx < G4) {
        int jj = idx >> 2, pp = idx & 3;
        int s = pp * HH + jj;
        g_b2[idx] = bih[s] + bhh[s];
    }
}

__global__ void init_kernel(float* __restrict__ hidden_out)
{
    int idx = blockIdx.x * blockDim.x + threadIdx.x;   // 0 .. 2*BH-1
    if (idx < BH) {
        g_hb_hi[0][idx] = __float2bfloat16(0.f);
        g_hb_lo[0][idx] = __float2bfloat16(0.f);
    }
    hidden_out[idx] = 0.f;   // hidden_out[t=0]
    if (idx < 4) { g_bar_cnt[idx] = 0; g_bar_gen[idx] = 0; }
}

// smem strides (bf16 elements)
#define SPAD 40     // A tiles: 40*2B = 80B, mult of 16B
#define WSTR 520    // resident weights: 520*2B, mult of 16B

// ---------------------------------------------------------------
// Input GEMM (split-bf16 x3): xgates = x @ Wih'^T + b'
// BM=128, BN=64, BK=32; 8 warps (4x2), warp tile 32x32.
// ---------------------------------------------------------------
#define XG_SMEM 32768
__global__ __launch_bounds__(256) void xgemm_kernel(const float* __restrict__ A)
{
    __shared__ __align__(16) char smem_raw[XG_SMEM];
    __nv_bfloat16* As_hi = (__nv_bfloat16*)smem_raw;                 // [128][40]
    __nv_bfloat16* As_lo = As_hi + 128 * SPAD;
    __nv_bfloat16* Bs_hi = As_lo + 128 * SPAD;                       // [64][40]
    __nv_bfloat16* Bs_lo = Bs_hi + 64 * SPAD;

    const int tid  = threadIdx.x;
    const int warp = tid >> 5;
    const int wr = warp >> 1, wc = warp & 1;
    const int m0 = blockIdx.y * 128;
    const int n0 = blockIdx.x * 64;

    wmma::fragment<wmma::accumulator, 16, 16, 16, float> acc[2][2];
#pragma unroll
    for (int i = 0; i < 2; i++)
#pragma unroll
        for (int j = 0; j < 2; j++) wmma::fill_fragment(acc[i][j], 0.f);

    for (int k0 = 0; k0 < IND; k0 += 32) {
#pragma unroll
        for (int i = 0; i < 4; i++) {
            int g = tid + i * 256;
            int m = g >> 3, kk = (g & 7) << 2;
            float4 v = *reinterpret_cast<const float4*>(&A[(size_t)(m0 + m) * IND + k0 + kk]);
            __nv_bfloat16 h0,l0,h1,l1,h2,l2,h3,l3;
            split_bf16(v.x,h0,l0); split_bf16(v.y,h1,l1);
            split_bf16(v.z,h2,l2); split_bf16(v.w,h3,l3);
            __nv_bfloat162* dh = (__nv_bfloat162*)&As_hi[m * SPAD + kk];
            __nv_bfloat162* dl = (__nv_bfloat162*)&As_lo[m * SPAD + kk];
            dh[0] = __nv_bfloat162(h0,h1); dh[1] = __nv_bfloat162(h2,h3);
            dl[0] = __nv_bfloat162(l0,l1); dl[1] = __nv_bfloat162(l2,l3);
        }
        {
            int n = tid >> 2, kk = (tid & 3) << 3;
            *reinterpret_cast<uint4*>(&Bs_hi[n * SPAD + kk]) =
                *reinterpret_cast<const uint4*>(&g_Wih_hi[(size_t)(n0 + n) * IND + k0 + kk]);
            *reinterpret_cast<uint4*>(&Bs_lo[n * SPAD + kk]) =
                *reinterpret_cast<const uint4*>(&g_Wih_lo[(size_t)(n0 + n) * IND + k0 + kk]);
        }
        __syncthreads();

#pragma unroll
        for (int ks = 0; ks < 32; ks += 16) {
            wmma::fragment<wmma::matrix_a, 16, 16, 16, __nv_bfloat16, wmma::row_major> ah[2], al[2];
            wmma::fragment<wmma::matrix_b, 16, 16, 16, __nv_bfloat16, wmma::col_major> bh[2], bl[2];
#pragma unroll
            for (int i = 0; i < 2; i++) {
                wmma::load_matrix_sync(ah[i], &As_hi[(wr * 32 + i * 16) * SPAD + ks], SPAD);
                wmma::load_matrix_sync(al[i], &As_lo[(wr * 32 + i * 16) * SPAD + ks], SPAD);
            }
#pragma unroll
            for (int j = 0; j < 2; j++) {
                wmma::load_matrix_sync(bh[j], &Bs_hi[(wc * 32 + j * 16) * SPAD + ks], SPAD);
                wmma::load_matrix_sync(bl[j], &Bs_lo[(wc * 32 + j * 16) * SPAD + ks], SPAD);
            }
#pragma unroll
            for (int i = 0; i < 2; i++)
#pragma unroll
                for (int j = 0; j < 2; j++) {
                    wmma::mma_sync(acc[i][j], ah[i], bh[j], acc[i][j]);
                    wmma::mma_sync(acc[i][j], ah[i], bl[j], acc[i][j]);
                    wmma::mma_sync(acc[i][j], al[i], bh[j], acc[i][j]);
                }
        }
        __syncthreads();
    }

    float* Cs = (float*)smem_raw;
#pragma unroll
    for (int i = 0; i < 2; i++)
#pragma unroll
        for (int j = 0; j < 2; j++)
            wmma::store_matrix_sync(&Cs[(wr * 32 + i * 16) * 64 + wc * 32 + j * 16],
                                    acc[i][j], 64, wmma::mem_row_major);
    __syncthreads();
#pragma unroll
    for (int i = 0; i < 8; i++) {
        int g = tid + i * 256;
        int r = g >> 4, c = (g & 15) << 2;
        float4 v = *reinterpret_cast<float4*>(&Cs[r * 64 + c]);
        v.x += g_b2[n0 + c + 0]; v.y += g_b2[n0 + c + 1];
        v.z += g_b2[n0 + c + 2]; v.w += g_b2[n0 + c + 3];
        *reinterpret_cast<float4*>(&g_xgates[(size_t)(m0 + r) * G4 + n0 + c]) = v;
    }
}

// ---------------------------------------------------------------
// Persistent scan kernel: all 256 steps, weights resident in smem.
// Grid (32 n-tiles, 4 m-tiles) = 128 CTAs, 128 threads, 1 CTA/SM.
// Dynamic smem layout (bytes):
//   [0)        Wh  resident Whh_hi [64][520]   66,560
//   [66560)    Wl  resident Whh_lo [64][520]   66,560
//   [133120)   A double buffer: 2 x (hi[64][40] + lo[64][40]) = 20,480
//   [153600)   Cs  [64][64] f32 = 16,384
// total 169,984
// ---------------------------------------------------------------
#define SC_W_OFF   0
#define SC_A_OFF   133120
#define SC_CS_OFF  153600
#define SC_SMEM    169984

__global__ __launch_bounds__(128, 1) void scan_kernel(const int* __restrict__ dones,
                                                      float* __restrict__ lstm_out,
                                                      float* __restrict__ hidden_out)
{
    extern __shared__ __align__(16) char sm[];
    __nv_bfloat16* Wh = (__nv_bfloat16*)(sm + SC_W_OFF);            // [64][520]
    __nv_bfloat16* Wl = Wh + 64 * WSTR;
    __nv_bfloat16* Ab = (__nv_bfloat16*)(sm + SC_A_OFF);            // 2 bufs
    float*         Cs = (float*)(sm + SC_CS_OFF);                   // [64][64]

    const int tid  = threadIdx.x;
    const int warp = tid >> 5;
    const int wr = warp >> 1, wc = warp & 1;       // 2x2 warp grid
    const int n0 = blockIdx.x * 64;                // gate-col tile (16 units)
    const int m0 = blockIdx.y * 64;                // batch tile
    const int grp = blockIdx.y;                    // barrier group

    // ---- load resident weight tile once: rows n0..n0+63, all K ----
#pragma unroll
    for (int i = 0; i < 32; i++) {
        int chunk = tid + i * 128;                 // 0..4095
        int r  = chunk >> 6;
        int kk = (chunk & 63) << 3;
        *reinterpret_cast<uint4*>(&Wh[r * WSTR + kk]) =
            *reinterpret_cast<const uint4*>(&g_Whh_hi[(size_t)(n0 + r) * HH + kk]);
        *reinterpret_cast<uint4*>(&Wl[r * WSTR + kk]) =
            *reinterpret_cast<const uint4*>(&g_Whh_lo[(size_t)(n0 + r) * HH + kk]);
    }
    __syncthreads();

    // ---- per-thread cell state (CTA exclusively owns its 64x16 block) ----
    float c_reg[8];
#pragma unroll
    for (int e = 0; e < 8; e++) c_reg[e] = 0.f;

    for (int t = 0; t < TT; t++) {
        const int rb = t & 1;                      // read h buffer
        const int wb = (t + 1) & 1;                // write h buffer

        // prefetch xgates tile for the epilogue (matches pointwise mapping)
        float4 xg[8];
#pragma unroll
        for (int e = 0; e < 8; e++) {
            int p  = tid + e * 128;
            int bl = p >> 4, u = p & 15;
            xg[e] = *reinterpret_cast<const float4*>(
                &g_xgates[((size_t)t * BB + m0 + bl) * G4 + n0 + (u << 2)]);
        }

        wmma::fragment<wmma::accumulator, 16, 16, 16, float> acc[2][2];
#pragma unroll
        for (int i = 0; i < 2; i++)
#pragma unroll
            for (int j = 0; j < 2; j++) wmma::fill_fragment(acc[i][j], 0.f);

        if (t > 0) {
            const __nv_bfloat16* srcH = g_hb_hi[rb];
            const __nv_bfloat16* srcL = g_hb_lo[rb];

            // stage k-tile 0
            {
                __nv_bfloat16* Ah = Ab;            // buf 0
                __nv_bfloat16* Al = Ab + 64 * SPAD;
#pragma unroll
                for (int i = 0; i < 2; i++) {
                    int chunk = tid + i * 128;     // 0..255
                    int row = chunk >> 2, kk = (chunk & 3) << 3;
                    cp16(&Ah[row * SPAD + kk], &srcH[(size_t)(m0 + row) * HH + kk]);
                    cp16(&Al[row * SPAD + kk], &srcL[(size_t)(m0 + row) * HH + kk]);
                }
                CP_COMMIT();
            }

            for (int kt = 0; kt < 16; kt++) {
                if (kt < 15) {                     // stage next tile
                    int nb = (kt + 1) & 1, k0n = (kt + 1) * 32;
                    __nv_bfloat16* Ah = Ab + nb * (128 * SPAD);
                    __nv_bfloat16* Al = Ah + 64 * SPAD;
#pragma unroll
                    for (int i = 0; i < 2; i++) {
                        int chunk = tid + i * 128;
                        int row = chunk >> 2, kk = (chunk & 3) << 3;
                        cp16(&Ah[row * SPAD + kk], &srcH[(size_t)(m0 + row) * HH + k0n + kk]);
                        cp16(&Al[row * SPAD + kk], &srcL[(size_t)(m0 + row) * HH + k0n + kk]);
                    }
                    CP_COMMIT();
                    CP_WAIT(1);
                } else {
                    CP_WAIT(0);
                }
                __syncthreads();

                const int cb = kt & 1, k0 = kt * 32;
                __nv_bfloat16* Ah = Ab + cb * (128 * SPAD);
                __nv_bfloat16* Al = Ah + 64 * SPAD;
#pragma unroll
                for (int ks = 0; ks < 32; ks += 16) {
                    wmma::fragment<wmma::matrix_a, 16, 16, 16, __nv_bfloat16, wmma::row_major> ah[2], al[2];
                    wmma::fragment<wmma::matrix_b, 16, 16, 16, __nv_bfloat16, wmma::col_major> bh[2], bl[2];
#pragma unroll
                    for (int i = 0; i < 2; i++) {
                        wmma::load_matrix_sync(ah[i], &Ah[(wr * 32 + i * 16) * SPAD + ks], SPAD);
                        wmma::load_matrix_sync(al[i], &Al[(wr * 32 + i * 16) * SPAD + ks], SPAD);
                    }
#pragma unroll
                    for (int j = 0; j < 2; j++) {
                        wmma::load_matrix_sync(bh[j], &Wh[(wc * 32 + j * 16) * WSTR + k0 + ks], WSTR);
                        wmma::load_matrix_sync(bl[j], &Wl[(wc * 32 + j * 16) * WSTR + k0 + ks], WSTR);
                    }
#pragma unroll
                    for (int i = 0; i < 2; i++)
#pragma unroll
                        for (int j = 0; j < 2; j++) {
                            wmma::mma_sync(acc[i][j], ah[i], bh[j], acc[i][j]);
                            wmma::mma_sync(acc[i][j], ah[i], bl[j], acc[i][j]);
                            wmma::mma_sync(acc[i][j], al[i], bh[j], acc[i][j]);
                        }
                }
                __syncthreads();
            }
        }

        // ---- stash recurrent contribution ----
#pragma unroll
        for (int i = 0; i < 2; i++)
#pragma unroll
            for (int j = 0; j < 2; j++)
                wmma::store_matrix_sync(&Cs[(wr * 32 + i * 16) * 64 + wc * 32 + j * 16],
                                        acc[i][j], 64, wmma::mem_row_major);
        __syncthreads();

        // ---- LSTM pointwise: 64 batches x 16 units, 8 per thread ----
#pragma unroll
        for (int e = 0; e < 8; e++) {
            int p  = tid + e * 128;
            int bl = p >> 4, u = p & 15;
            int b  = m0 + bl;
            int j  = (n0 >> 2) + u;

            float4 rec = *reinterpret_cast<float4*>(&Cs[bl * 64 + (u << 2)]);

            float ig = rec.x + xg[e].x;
            float fg = rec.y + xg[e].y;
            float gg = rec.z + xg[e].z;
            float og = rec.w + xg[e].w;

            float c  = c_reg[e];
            float cn = sigf(fg) * c + sigf(ig) * tanhf(gg);
            float hn = sigf(og) * tanhf(cn);

            int sidx = b * HH + j;
            lstm_out[(size_t)t * BH + sidx] = hn;

            if (t + 1 < TT) {
                float keep = 1.f - (float)dones[(t + 1) * BB + b];
                hn *= keep;
                cn *= keep;
                hidden_out[(size_t)(t + 1) * 2 * BH + sidx]      = hn;
                hidden_out[(size_t)(t + 1) * 2 * BH + BH + sidx] = cn;
            }
            c_reg[e] = cn;

            __nv_bfloat16 hi, lo;
            split_bf16(hn, hi, lo);
            g_hb_hi[wb][sidx] = hi;
            g_hb_lo[wb][sidx] = lo;
        }

        // ---- inter-step barrier within the m-group (32 CTAs) ----
        __syncthreads();
        if (tid == 0) {
            __threadfence();
            unsigned prev = atomicAdd((unsigned*)&g_bar_cnt[grp], 1);
            if (prev == 31) {
                g_bar_cnt[grp] = 0;
                __threadfence();
                atomicAdd((unsigned*)&g_bar_gen[grp], 1);
            } else {
                unsigned target = (unsigned)(t + 1);
                while (g_bar_gen[grp] < target) { __nanosleep(60); }
            }
        }
        __syncthreads();
    }
}

// ---------------------------------------------------------------
extern "C" void kernel_launch(void* const* d_in, const int* in_sizes, int n_in,
                              void* d_out, int out_size)
{
    const float* x     = (const float*)d_in[0];   // [T,B,IN]
    const int*   dones = (const int*)  d_in[1];   // [T,B]
    const float* W_ih  = (const float*)d_in[2];   // [4H,IN]
    const float* W_hh  = (const float*)d_in[3];   // [4H,H]
    const float* b_ih  = (const float*)d_in[4];   // [4H]
    const float* b_hh  = (const float*)d_in[5];   // [4H]

    float* out        = (float*)d_out;
    float* lstm_out   = out;                       // [T,B,H]
    float* hidden_out = out + (size_t)TT * BH;     // [T,2,B,H]

    cudaFuncSetAttribute(scan_kernel, cudaFuncAttributeMaxDynamicSharedMemorySize, SC_SMEM);

    // 0) weight reorder + bf16 split + bias merge
    reorder_kernel<<<(G4 * IND) / 256, 256>>>(W_ih, W_hh, b_ih, b_hh);

    // 1) zero h buffers, barrier state, hidden_out[0]
    init_kernel<<<(2 * BH) / 256, 256>>>(hidden_out);

    // 2) time-parallel input GEMM (bf16x3 tensor cores)
    {
        dim3 grid(G4 / 64, MROWS / 128);
        xgemm_kernel<<<grid, 256>>>(x);
    }

    // 3) persistent fused recurrent scan (all 256 steps in one launch)
    {
        dim3 grid(G4 / 64, BB / 64);   // (32, 4) = 128 CTAs, 1 per SM
        scan_kernel<<<grid, 128, SC_SMEM>>>(dones, lstm_out, hidden_out);
    }
}

// round 11
// speedup vs baseline: 3.4806x; 1.0550x over previous
#include <cuda_runtime.h>
#include <cuda_bf16.h>
#include <cstdint>
#include <math.h>
#include <mma.h>
using namespace nvcuda;

// Problem constants: T=256, B=256, IN=512, H=512
#define TT  256
#define BB  256
#define IND 512
#define HH  512
#define G4  (4*HH)          // 2048 gate columns
#define BH  (BB*HH)         // 131072 state elements
#define MROWS (TT*BB)       // 65536 rows for the input GEMM

// -------- persistent device scratch (no cudaMalloc allowed) --------
__device__ float g_xgates[(size_t)MROWS * G4];            // 512 MB
__device__ __nv_bfloat16 g_Wih_hi[(size_t)G4 * IND];      // gate-interleaved splits
__device__ __nv_bfloat16 g_Wih_lo[(size_t)G4 * IND];
__device__ __nv_bfloat16 g_Whh_hi[(size_t)G4 * HH];
__device__ __nv_bfloat16 g_Whh_lo[(size_t)G4 * HH];
__device__ float g_b2[G4];                                // merged bias
__device__ __nv_bfloat16 g_hb_hi[2][BH];                  // h ping-pong, pre-split
__device__ __nv_bfloat16 g_hb_lo[2][BH];
__device__ volatile unsigned g_bar_cnt[4];                // per-m-group barrier
__device__ volatile unsigned g_bar_gen[4];

__device__ __forceinline__ float sigf(float x) { return 1.f / (1.f + expf(-x)); }

__device__ __forceinline__ void split_bf16(float v, __nv_bfloat16& hi, __nv_bfloat16& lo) {
    hi = __float2bfloat16(v);
    lo = __float2bfloat16(v - __bfloat162float(hi));
}

__device__ __forceinline__ void cp16(void* dst_smem, const void* src) {
    unsigned int d = (unsigned int)__cvta_generic_to_shared(dst_smem);
    asm volatile("cp.async.cg.shared.global [%0], [%1], 16;" :: "r"(d), "l"(src));
}
#define CP_COMMIT()  asm volatile("cp.async.commit_group;")
#define CP_WAIT(N)   asm volatile("cp.async.wait_group %0;" :: "n"(N))

// ---------------------------------------------------------------
// Reorder weights gate-interleaved (new row 4j+p <- old row p*H+j),
// split into bf16 hi/lo, merge biases.
// ---------------------------------------------------------------
__global__ void reorder_kernel(const float* __restrict__ Wih,
                               const float* __restrict__ Whh,
                               const float* __restrict__ bih,
                               const float* __restrict__ bhh)
{
    int idx = blockIdx.x * blockDim.x + threadIdx.x;  // over G4*512
    int row = idx >> 9;
    int k   = idx & 511;
    int j = row >> 2, p = row & 3;
    int src = p * HH + j;

    __nv_bfloat16 hi, lo;
    split_bf16(Wih[(size_t)src * IND + k], hi, lo);
    g_Wih_hi[idx] = hi; g_Wih_lo[idx] = lo;
    split_bf16(Whh[(size_t)src * HH + k], hi, lo);
    g_Whh_hi[idx] = hi; g_Whh_lo[idx] = lo;

    if (idx < G4) {
        int jj = idx >> 2, pp = idx & 3;
        int s = pp * HH + jj;
        g_b2[idx] = bih[s] + bhh[s];
    }
}

__global__ void init_kernel(float* __restrict__ hidden_out)
{
    int idx = blockIdx.x * blockDim.x + threadIdx.x;   // 0 .. 2*BH-1
    if (idx < BH) {
        g_hb_hi[0][idx] = __float2bfloat16(0.f);
        g_hb_lo[0][idx] = __float2bfloat16(0.f);
    }
    hidden_out[idx] = 0.f;   // hidden_out[t=0]
    if (idx < 4) { g_bar_cnt[idx] = 0; g_bar_gen[idx] = 0; }
}

// smem strides (bf16 elements)
#define SPAD 40     // xgemm A tiles: 80B rows
#define WSTR 520    // resident weights: 1040B rows
#define SA   72     // scan A tiles (BK=64): 144B rows

// ---------------------------------------------------------------
// Input GEMM (split-bf16 x3): xgates = x @ Wih'^T + b'  (unchanged)
// ---------------------------------------------------------------
#define XG_SMEM 32768
__global__ __launch_bounds__(256) void xgemm_kernel(const float* __restrict__ A)
{
    __shared__ __align__(16) char smem_raw[XG_SMEM];
    __nv_bfloat16* As_hi = (__nv_bfloat16*)smem_raw;                 // [128][40]
    __nv_bfloat16* As_lo = As_hi + 128 * SPAD;
    __nv_bfloat16* Bs_hi = As_lo + 128 * SPAD;                       // [64][40]
    __nv_bfloat16* Bs_lo = Bs_hi + 64 * SPAD;

    const int tid  = threadIdx.x;
    const int warp = tid >> 5;
    const int wr = warp >> 1, wc = warp & 1;
    const int m0 = blockIdx.y * 128;
    const int n0 = blockIdx.x * 64;

    wmma::fragment<wmma::accumulator, 16, 16, 16, float> acc[2][2];
#pragma unroll
    for (int i = 0; i < 2; i++)
#pragma unroll
        for (int j = 0; j < 2; j++) wmma::fill_fragment(acc[i][j], 0.f);

    for (int k0 = 0; k0 < IND; k0 += 32) {
#pragma unroll
        for (int i = 0; i < 4; i++) {
            int g = tid + i * 256;
            int m = g >> 3, kk = (g & 7) << 2;
            float4 v = *reinterpret_cast<const float4*>(&A[(size_t)(m0 + m) * IND + k0 + kk]);
            __nv_bfloat16 h0,l0,h1,l1,h2,l2,h3,l3;
            split_bf16(v.x,h0,l0); split_bf16(v.y,h1,l1);
            split_bf16(v.z,h2,l2); split_bf16(v.w,h3,l3);
            __nv_bfloat162* dh = (__nv_bfloat162*)&As_hi[m * SPAD + kk];
            __nv_bfloat162* dl = (__nv_bfloat162*)&As_lo[m * SPAD + kk];
            dh[0] = __nv_bfloat162(h0,h1); dh[1] = __nv_bfloat162(h2,h3);
            dl[0] = __nv_bfloat162(l0,l1); dl[1] = __nv_bfloat162(l2,l3);
        }
        {
            int n = tid >> 2, kk = (tid & 3) << 3;
            *reinterpret_cast<uint4*>(&Bs_hi[n * SPAD + kk]) =
                *reinterpret_cast<const uint4*>(&g_Wih_hi[(size_t)(n0 + n) * IND + k0 + kk]);
            *reinterpret_cast<uint4*>(&Bs_lo[n * SPAD + kk]) =
                *reinterpret_cast<const uint4*>(&g_Wih_lo[(size_t)(n0 + n) * IND + k0 + kk]);
        }
        __syncthreads();

#pragma unroll
        for (int ks = 0; ks < 32; ks += 16) {
            wmma::fragment<wmma::matrix_a, 16, 16, 16, __nv_bfloat16, wmma::row_major> ah[2], al[2];
            wmma::fragment<wmma::matrix_b, 16, 16, 16, __nv_bfloat16, wmma::col_major> bh[2], bl[2];
#pragma unroll
            for (int i = 0; i < 2; i++) {
                wmma::load_matrix_sync(ah[i], &As_hi[(wr * 32 + i * 16) * SPAD + ks], SPAD);
                wmma::load_matrix_sync(al[i], &As_lo[(wr * 32 + i * 16) * SPAD + ks], SPAD);
            }
#pragma unroll
            for (int j = 0; j < 2; j++) {
                wmma::load_matrix_sync(bh[j], &Bs_hi[(wc * 32 + j * 16) * SPAD + ks], SPAD);
                wmma::load_matrix_sync(bl[j], &Bs_lo[(wc * 32 + j * 16) * SPAD + ks], SPAD);
            }
            // term-outer order: max dependency distance per accumulator
#pragma unroll
            for (int i = 0; i < 2; i++)
#pragma unroll
                for (int j = 0; j < 2; j++) wmma::mma_sync(acc[i][j], ah[i], bh[j], acc[i][j]);
#pragma unroll
            for (int i = 0; i < 2; i++)
#pragma unroll
                for (int j = 0; j < 2; j++) wmma::mma_sync(acc[i][j], ah[i], bl[j], acc[i][j]);
#pragma unroll
            for (int i = 0; i < 2; i++)
#pragma unroll
                for (int j = 0; j < 2; j++) wmma::mma_sync(acc[i][j], al[i], bh[j], acc[i][j]);
        }
        __syncthreads();
    }

    float* Cs = (float*)smem_raw;
#pragma unroll
    for (int i = 0; i < 2; i++)
#pragma unroll
        for (int j = 0; j < 2; j++)
            wmma::store_matrix_sync(&Cs[(wr * 32 + i * 16) * 64 + wc * 32 + j * 16],
                                    acc[i][j], 64, wmma::mem_row_major);
    __syncthreads();
#pragma unroll
    for (int i = 0; i < 8; i++) {
        int g = tid + i * 256;
        int r = g >> 4, c = (g & 15) << 2;
        float4 v = *reinterpret_cast<float4*>(&Cs[r * 64 + c]);
        v.x += g_b2[n0 + c + 0]; v.y += g_b2[n0 + c + 1];
        v.z += g_b2[n0 + c + 2]; v.w += g_b2[n0 + c + 3];
        *reinterpret_cast<float4*>(&g_xgates[(size_t)(m0 + r) * G4 + n0 + c]) = v;
    }
}

// ---------------------------------------------------------------
// Persistent scan kernel v2: 256 threads, BK=64, 3-stage cp.async
// pipeline, one __syncthreads per k-tile, term-outer MMA order.
// Grid (32 n-tiles, 4 m-tiles) = 128 CTAs, 1 CTA/SM.
// smem: W 133,120 | A 3 stages x 18,432 = 55,296 | Cs 16,384  -> 204,800
// ---------------------------------------------------------------
#define SC_W_OFF   0
#define SC_A_OFF   133120
#define SC_CS_OFF  188416
#define SC_SMEM    204800
#define A_STAGE_ELEMS (2 * 64 * SA)        // hi+lo per stage (bf16 elems)
#define NKT 8                              // 512 / 64

__global__ __launch_bounds__(256, 1) void scan_kernel(const int* __restrict__ dones,
                                                      float* __restrict__ lstm_out,
                                                      float* __restrict__ hidden_out)
{
    extern __shared__ __align__(16) char sm[];
    __nv_bfloat16* Wh = (__nv_bfloat16*)(sm + SC_W_OFF);            // [64][520]
    __nv_bfloat16* Wl = Wh + 64 * WSTR;
    __nv_bfloat16* Ab = (__nv_bfloat16*)(sm + SC_A_OFF);            // 3 stages
    float*         Cs = (float*)(sm + SC_CS_OFF);                   // [64][64]

    const int tid  = threadIdx.x;
    const int warp = tid >> 5;
    const int wr = warp >> 2, wc = warp & 3;       // 2x4 warp grid, tile 32x16
    const int n0 = blockIdx.x * 64;                // gate-col tile (16 units)
    const int m0 = blockIdx.y * 64;                // batch tile
    const int grp = blockIdx.y;                    // barrier group

    // ---- load resident weight tile once ----
#pragma unroll
    for (int i = 0; i < 16; i++) {
        int chunk = tid + i * 256;                 // 0..4095
        int r  = chunk >> 6;
        int kk = (chunk & 63) << 3;
        *reinterpret_cast<uint4*>(&Wh[r * WSTR + kk]) =
            *reinterpret_cast<const uint4*>(&g_Whh_hi[(size_t)(n0 + r) * HH + kk]);
        *reinterpret_cast<uint4*>(&Wl[r * WSTR + kk]) =
            *reinterpret_cast<const uint4*>(&g_Whh_lo[(size_t)(n0 + r) * HH + kk]);
    }
    __syncthreads();

    // ---- per-thread cell state (CTA owns its 64x16 block; 4 elems/thread) ----
    float c_reg[4];
#pragma unroll
    for (int e = 0; e < 4; e++) c_reg[e] = 0.f;

    for (int t = 0; t < TT; t++) {
        const int rb = t & 1;                      // read h buffer
        const int wb = (t + 1) & 1;                // write h buffer

        // prefetch xgates tile (4 float4 per thread, matches pointwise map)
        float4 xg[4];
#pragma unroll
        for (int e = 0; e < 4; e++) {
            int p  = tid + e * 256;
            int bl = p >> 4, u = p & 15;
            xg[e] = *reinterpret_cast<const float4*>(
                &g_xgates[((size_t)t * BB + m0 + bl) * G4 + n0 + (u << 2)]);
        }

        wmma::fragment<wmma::accumulator, 16, 16, 16, float> acc[2];
#pragma unroll
        for (int i = 0; i < 2; i++) wmma::fill_fragment(acc[i], 0.f);

        if (t > 0) {
            const __nv_bfloat16* srcH = g_hb_hi[rb];
            const __nv_bfloat16* srcL = g_hb_lo[rb];

            // stage s: 64x64 hi + lo = 1024 cp16; 4 per thread
            auto stage = [&](int kt, int s) {
                __nv_bfloat16* Ah = Ab + s * A_STAGE_ELEMS;
                __nv_bfloat16* Al = Ah + 64 * SA;
                int k0 = kt * 64;
#pragma unroll
                for (int i = 0; i < 2; i++) {
                    int chunk = tid + i * 256;     // 0..511
                    int row = chunk >> 3, kk = (chunk & 7) << 3;
                    cp16(&Ah[row * SA + kk], &srcH[(size_t)(m0 + row) * HH + k0 + kk]);
                    cp16(&Al[row * SA + kk], &srcL[(size_t)(m0 + row) * HH + k0 + kk]);
                }
                CP_COMMIT();
            };

            stage(0, 0);
            stage(1, 1);

            for (int kt = 0; kt < NKT; kt++) {
                if (kt < NKT - 1) { CP_WAIT(1); } else { CP_WAIT(0); }
                __syncthreads();
                if (kt + 2 < NKT) stage(kt + 2, (kt + 2) % 3);

                const __nv_bfloat16* Ah = Ab + (kt % 3) * A_STAGE_ELEMS;
                const __nv_bfloat16* Al = Ah + 64 * SA;
                const int k0 = kt * 64;
#pragma unroll
                for (int ks = 0; ks < 64; ks += 16) {
                    wmma::fragment<wmma::matrix_a, 16, 16, 16, __nv_bfloat16, wmma::row_major> ah[2], al[2];
                    wmma::fragment<wmma::matrix_b, 16, 16, 16, __nv_bfloat16, wmma::col_major> bh, bl;
#pragma unroll
                    for (int i = 0; i < 2; i++) {
                        wmma::load_matrix_sync(ah[i], &Ah[(wr * 32 + i * 16) * SA + ks], SA);
                        wmma::load_matrix_sync(al[i], &Al[(wr * 32 + i * 16) * SA + ks], SA);
                    }
                    wmma::load_matrix_sync(bh, &Wh[(wc * 16) * WSTR + k0 + ks], WSTR);
                    wmma::load_matrix_sync(bl, &Wl[(wc * 16) * WSTR + k0 + ks], WSTR);

                    // term-outer: dependency distance 2 per acc, 2 warps/SMSP
                    wmma::mma_sync(acc[0], ah[0], bh, acc[0]);
                    wmma::mma_sync(acc[1], ah[1], bh, acc[1]);
                    wmma::mma_sync(acc[0], ah[0], bl, acc[0]);
                    wmma::mma_sync(acc[1], ah[1], bl, acc[1]);
                    wmma::mma_sync(acc[0], al[0], bh, acc[0]);
                    wmma::mma_sync(acc[1], al[1], bh, acc[1]);
                }
            }
            __syncthreads();   // MMAs done before Cs overwrite (Cs disjoint, but
                               // also guards next-step stage(0) vs last MMA reads)
        }

        // ---- stash recurrent contribution ----
#pragma unroll
        for (int i = 0; i < 2; i++)
            wmma::store_matrix_sync(&Cs[(wr * 32 + i * 16) * 64 + wc * 16],
                                    acc[i], 64, wmma::mem_row_major);
        __syncthreads();

        // ---- LSTM pointwise: 64 batches x 16 units, 4 per thread ----
#pragma unroll
        for (int e = 0; e < 4; e++) {
            int p  = tid + e * 256;
            int bl = p >> 4, u = p & 15;
            int b  = m0 + bl;
            int j  = (n0 >> 2) + u;

            float4 rec = *reinterpret_cast<float4*>(&Cs[bl * 64 + (u << 2)]);

            float ig = rec.x + xg[e].x;
            float fg = rec.y + xg[e].y;
            float gg = rec.z + xg[e].z;
            float og = rec.w + xg[e].w;

            float c  = c_reg[e];
            float cn = sigf(fg) * c + sigf(ig) * tanhf(gg);
            float hn = sigf(og) * tanhf(cn);

            int sidx = b * HH + j;
            lstm_out[(size_t)t * BH + sidx] = hn;

            if (t + 1 < TT) {
                float keep = 1.f - (float)dones[(t + 1) * BB + b];
                hn *= keep;
                cn *= keep;
                hidden_out[(size_t)(t + 1) * 2 * BH + sidx]      = hn;
                hidden_out[(size_t)(t + 1) * 2 * BH + BH + sidx] = cn;
            }
            c_reg[e] = cn;

            __nv_bfloat16 hi, lo;
            split_bf16(hn, hi, lo);
            g_hb_hi[wb][sidx] = hi;
            g_hb_lo[wb][sidx] = lo;
        }

        // ---- inter-step barrier within the m-group (32 CTAs) ----
        __syncthreads();
        if (tid == 0) {
            __threadfence();
            unsigned prev = atomicAdd((unsigned*)&g_bar_cnt[grp], 1);
            if (prev == 31) {
                g_bar_cnt[grp] = 0;
                __threadfence();
                atomicAdd((unsigned*)&g_bar_gen[grp], 1);
            } else {
                unsigned target = (unsigned)(t + 1);
                while (g_bar_gen[grp] < target) { __nanosleep(60); }
            }
        }
        __syncthreads();
    }
}

// ---------------------------------------------------------------
extern "C" void kernel_launch(void* const* d_in, const int* in_sizes, int n_in,
                              void* d_out, int out_size)
{
    const float* x     = (const float*)d_in[0];   // [T,B,IN]
    const int*   dones = (const int*)  d_in[1];   // [T,B]
    const float* W_ih  = (const float*)d_in[2];   // [4H,IN]
    const float* W_hh  = (const float*)d_in[3];   // [4H,H]
    const float* b_ih  = (const float*)d_in[4];   // [4H]
    const float* b_hh  = (const float*)d_in[5];   // [4H]

    float* out        = (float*)d_out;
    float* lstm_out   = out;                       // [T,B,H]
    float* hidden_out = out + (size_t)TT * BH;     // [T,2,B,H]

    cudaFuncSetAttribute(scan_kernel, cudaFuncAttributeMaxDynamicSharedMemorySize, SC_SMEM);

    // 0) weight reorder + bf16 split + bias merge
    reorder_kernel<<<(G4 * IND) / 256, 256>>>(W_ih, W_hh, b_ih, b_hh);

    // 1) zero h buffers, barrier state, hidden_out[0]
    init_kernel<<<(2 * BH) / 256, 256>>>(hidden_out);

    // 2) time-parallel input GEMM (bf16x3 tensor cores)
    {
        dim3 grid(G4 / 64, MROWS / 128);
        xgemm_kernel<<<grid, 256>>>(x);
    }

    // 3) persistent fused recurrent scan (all 256 steps in one launch)
    {
        dim3 grid(G4 / 64, BB / 64);   // (32, 4) = 128 CTAs, 1 per SM
        scan_kernel<<<grid, 256, SC_SMEM>>>(dones, lstm_out, hidden_out);
    }
}

// round 15
// speedup vs baseline: 3.5096x; 1.0084x over previous
#include <cuda_runtime.h>
#include <cuda_bf16.h>
#include <cstdint>
#include <math.h>
#include <mma.h>
using namespace nvcuda;

// Problem constants: T=256, B=256, IN=512, H=512
#define TT  256
#define BB  256
#define IND 512
#define HH  512
#define G4  (4*HH)          // 2048 gate columns
#define BH  (BB*HH)         // 131072 state elements
#define MROWS (TT*BB)       // 65536 rows for the input GEMM

// -------- persistent device scratch (no cudaMalloc allowed) --------
__device__ float g_xgates[(size_t)MROWS * G4];            // 512 MB
__device__ __nv_bfloat16 g_x_hi[(size_t)MROWS * IND];     // x split (64 MB each)
__device__ __nv_bfloat16 g_x_lo[(size_t)MROWS * IND];
__device__ __nv_bfloat16 g_Wih_hi[(size_t)G4 * IND];      // gate-interleaved splits
__device__ __nv_bfloat16 g_Wih_lo[(size_t)G4 * IND];
__device__ __nv_bfloat16 g_Whh_hi[(size_t)G4 * HH];
__device__ __nv_bfloat16 g_Whh_lo[(size_t)G4 * HH];
__device__ float g_b2[G4];                                // merged bias
__device__ __nv_bfloat16 g_hb_hi[2][BH];                  // h ping-pong, pre-split
__device__ __nv_bfloat16 g_hb_lo[2][BH];
__device__ volatile unsigned g_bar_cnt[4];                // per-m-group barrier
__device__ volatile unsigned g_bar_gen[4];

__device__ __forceinline__ float sigf(float x) { return 1.f / (1.f + expf(-x)); }

__device__ __forceinline__ void split_bf16(float v, __nv_bfloat16& hi, __nv_bfloat16& lo) {
    hi = __float2bfloat16(v);
    lo = __float2bfloat16(v - __bfloat162float(hi));
}

__device__ __forceinline__ void cp16(void* dst_smem, const void* src) {
    unsigned int d = (unsigned int)__cvta_generic_to_shared(dst_smem);
    asm volatile("cp.async.cg.shared.global [%0], [%1], 16;" :: "r"(d), "l"(src));
}
#define CP_COMMIT()  asm volatile("cp.async.commit_group;")
#define CP_WAIT(N)   asm volatile("cp.async.wait_group %0;" :: "n"(N))

// ---------------------------------------------------------------
// Reorder weights gate-interleaved (new row 4j+p <- old row p*H+j),
// split into bf16 hi/lo, merge biases.
// ---------------------------------------------------------------
__global__ void reorder_kernel(const float* __restrict__ Wih,
                               const float* __restrict__ Whh,
                               const float* __restrict__ bih,
                               const float* __restrict__ bhh)
{
    int idx = blockIdx.x * blockDim.x + threadIdx.x;  // over G4*512
    int row = idx >> 9;
    int k   = idx & 511;
    int j = row >> 2, p = row & 3;
    int src = p * HH + j;

    __nv_bfloat16 hi, lo;
    split_bf16(Wih[(size_t)src * IND + k], hi, lo);
    g_Wih_hi[idx] = hi; g_Wih_lo[idx] = lo;
    split_bf16(Whh[(size_t)src * HH + k], hi, lo);
    g_Whh_hi[idx] = hi; g_Whh_lo[idx] = lo;

    if (idx < G4) {
        int jj = idx >> 2, pp = idx & 3;
        int s = pp * HH + jj;
        g_b2[idx] = bih[s] + bhh[s];
    }
}

// split x (fp32 -> bf16 hi/lo), row-major preserved
__global__ void splitx_kernel(const float* __restrict__ x)
{
    size_t i4 = (size_t)blockIdx.x * blockDim.x + threadIdx.x;   // float4 index
    float4 v = reinterpret_cast<const float4*>(x)[i4];
    __nv_bfloat16 h0,l0,h1,l1,h2,l2,h3,l3;
    split_bf16(v.x,h0,l0); split_bf16(v.y,h1,l1);
    split_bf16(v.z,h2,l2); split_bf16(v.w,h3,l3);
    __nv_bfloat162* dh = reinterpret_cast<__nv_bfloat162*>(g_x_hi) + i4 * 2;
    __nv_bfloat162* dl = reinterpret_cast<__nv_bfloat162*>(g_x_lo) + i4 * 2;
    dh[0] = __nv_bfloat162(h0,h1); dh[1] = __nv_bfloat162(h2,h3);
    dl[0] = __nv_bfloat162(l0,l1); dl[1] = __nv_bfloat162(l2,l3);
}

__global__ void init_kernel(float* __restrict__ hidden_out)
{
    int idx = blockIdx.x * blockDim.x + threadIdx.x;   // 0 .. 2*BH-1
    if (idx < BH) {
        g_hb_hi[0][idx] = __float2bfloat16(0.f);
        g_hb_lo[0][idx] = __float2bfloat16(0.f);
    }
    hidden_out[idx] = 0.f;   // hidden_out[t=0]
    if (idx < 4) { g_bar_cnt[idx] = 0; g_bar_gen[idx] = 0; }
}

// smem strides (bf16 elements)
#define SPAD 40     // BK=32 tiles: 80B rows
#define WSTR 520    // resident weights: 1040B rows
#define SA   72     // scan A tiles (BK=64): 144B rows

// ---------------------------------------------------------------
// Input GEMM v3 (split-bf16 x3, wmma): xgates = x @ Wih'^T + b'
// BM=128, BN=64, BK=32; 256 thr (8 warps 4x2, warp tile 32x32).
// Pre-split A (g_x_hi/lo), 3-stage cp.async, one sync per k-tile.
// Stage: Ah 10240 | Al 10240 | Bh 5120 | Bl 5120 = 30720 B; x3 = 92160.
// 2 CTAs/SM (launch_bounds) -> 184 KB smem/SM.
// ---------------------------------------------------------------
#define XSTAGE_B 30720
#define XG_SMEM  (3 * XSTAGE_B)
#define XNKT 16

__global__ __launch_bounds__(256, 2) void xgemm_kernel()
{
    extern __shared__ __align__(16) char xsm[];

    const int tid  = threadIdx.x;
    const int warp = tid >> 5;
    const int wr = warp >> 1, wc = warp & 1;       // 4x2 warp grid
    const int n0 = blockIdx.x * 64;
    const int m0 = blockIdx.y * 128;

    wmma::fragment<wmma::accumulator, 16, 16, 16, float> acc[2][2];
#pragma unroll
    for (int i = 0; i < 2; i++)
#pragma unroll
        for (int j = 0; j < 2; j++) wmma::fill_fragment(acc[i][j], 0.f);

    // stage k-tile kt into buffer s. 6 cp16 per thread.
    auto stage = [&](int kt, int s) {
        char* b = xsm + s * XSTAGE_B;
        __nv_bfloat16* Ah = (__nv_bfloat16*)b;                 // [128][40]
        __nv_bfloat16* Al = Ah + 128 * SPAD;
        __nv_bfloat16* Bh = Al + 128 * SPAD;                   // [64][40]
        __nv_bfloat16* Bl = Bh + 64 * SPAD;
        const int k0 = kt * 32;
#pragma unroll
        for (int i = 0; i < 2; i++) {                          // A hi+lo: 512 each
            int chunk = tid + i * 256;
            int r = chunk >> 2, ke = (chunk & 3) << 3;         // elem col
            cp16(&Ah[r * SPAD + ke], &g_x_hi[(size_t)(m0 + r) * IND + k0 + ke]);
            cp16(&Al[r * SPAD + ke], &g_x_lo[(size_t)(m0 + r) * IND + k0 + ke]);
        }
        {                                                      // B hi+lo: 256 each
            int r = tid >> 2, ke = (tid & 3) << 3;
            cp16(&Bh[r * SPAD + ke], &g_Wih_hi[(size_t)(n0 + r) * IND + k0 + ke]);
            cp16(&Bl[r * SPAD + ke], &g_Wih_lo[(size_t)(n0 + r) * IND + k0 + ke]);
        }
        CP_COMMIT();
    };

    stage(0, 0);
    stage(1, 1);

    for (int kt = 0; kt < XNKT; kt++) {
        if (kt < XNKT - 1) { CP_WAIT(1); } else { CP_WAIT(0); }
        __syncthreads();
        if (kt + 2 < XNKT) stage(kt + 2, (kt + 2) % 3);

        char* b = xsm + (kt % 3) * XSTAGE_B;
        __nv_bfloat16* Ah = (__nv_bfloat16*)b;
        __nv_bfloat16* Al = Ah + 128 * SPAD;
        __nv_bfloat16* Bh = Al + 128 * SPAD;
        __nv_bfloat16* Bl = Bh + 64 * SPAD;

#pragma unroll
        for (int ks = 0; ks < 32; ks += 16) {
            wmma::fragment<wmma::matrix_a, 16, 16, 16, __nv_bfloat16, wmma::row_major> ah[2], al[2];
            wmma::fragment<wmma::matrix_b, 16, 16, 16, __nv_bfloat16, wmma::col_major> bh[2], bl[2];
#pragma unroll
            for (int i = 0; i < 2; i++) {
                wmma::load_matrix_sync(ah[i], &Ah[(wr * 32 + i * 16) * SPAD + ks], SPAD);
                wmma::load_matrix_sync(al[i], &Al[(wr * 32 + i * 16) * SPAD + ks], SPAD);
            }
#pragma unroll
            for (int j = 0; j < 2; j++) {
                wmma::load_matrix_sync(bh[j], &Bh[(wc * 32 + j * 16) * SPAD + ks], SPAD);
                wmma::load_matrix_sync(bl[j], &Bl[(wc * 32 + j * 16) * SPAD + ks], SPAD);
            }
            // term-outer: max dependency distance per accumulator
#pragma unroll
            for (int i = 0; i < 2; i++)
#pragma unroll
                for (int j = 0; j < 2; j++) wmma::mma_sync(acc[i][j], ah[i], bh[j], acc[i][j]);
#pragma unroll
            for (int i = 0; i < 2; i++)
#pragma unroll
                for (int j = 0; j < 2; j++) wmma::mma_sync(acc[i][j], ah[i], bl[j], acc[i][j]);
#pragma unroll
            for (int i = 0; i < 2; i++)
#pragma unroll
                for (int j = 0; j < 2; j++) wmma::mma_sync(acc[i][j], al[i], bh[j], acc[i][j]);
        }
    }
    __syncthreads();   // all MMAs done before smem reuse as Cs

    float* Cs = (float*)xsm;   // [128][64] = 32768 B < XG_SMEM
#pragma unroll
    for (int i = 0; i < 2; i++)
#pragma unroll
        for (int j = 0; j < 2; j++)
            wmma::store_matrix_sync(&Cs[(wr * 32 + i * 16) * 64 + wc * 32 + j * 16],
                                    acc[i][j], 64, wmma::mem_row_major);
    __syncthreads();
#pragma unroll
    for (int i = 0; i < 8; i++) {
        int g = tid + i * 256;
        int r = g >> 4, c = (g & 15) << 2;
        float4 v = *reinterpret_cast<float4*>(&Cs[r * 64 + c]);
        v.x += g_b2[n0 + c + 0]; v.y += g_b2[n0 + c + 1];
        v.z += g_b2[n0 + c + 2]; v.w += g_b2[n0 + c + 3];
        *reinterpret_cast<float4*>(&g_xgates[(size_t)(m0 + r) * G4 + n0 + c]) = v;
    }
}

// ---------------------------------------------------------------
// Persistent scan kernel (UNCHANGED from the passing R10 version).
// ---------------------------------------------------------------
#define SC_W_OFF   0
#define SC_A_OFF   133120
#define SC_CS_OFF  188416
#define SC_SMEM    204800
#define A_STAGE_ELEMS (2 * 64 * SA)
#define NKT 8

__global__ __launch_bounds__(256, 1) void scan_kernel(const int* __restrict__ dones,
                                                      float* __restrict__ lstm_out,
                                                      float* __restrict__ hidden_out)
{
    extern __shared__ __align__(16) char sm[];
    __nv_bfloat16* Wh = (__nv_bfloat16*)(sm + SC_W_OFF);
    __nv_bfloat16* Wl = Wh + 64 * WSTR;
    __nv_bfloat16* Ab = (__nv_bfloat16*)(sm + SC_A_OFF);
    float*         Cs = (float*)(sm + SC_CS_OFF);

    const int tid  = threadIdx.x;
    const int warp = tid >> 5;
    const int wr = warp >> 2, wc = warp & 3;
    const int n0 = blockIdx.x * 64;
    const int m0 = blockIdx.y * 64;
    const int grp = blockIdx.y;

#pragma unroll
    for (int i = 0; i < 16; i++) {
        int chunk = tid + i * 256;
        int r  = chunk >> 6;
        int kk = (chunk & 63) << 3;
        *reinterpret_cast<uint4*>(&Wh[r * WSTR + kk]) =
            *reinterpret_cast<const uint4*>(&g_Whh_hi[(size_t)(n0 + r) * HH + kk]);
        *reinterpret_cast<uint4*>(&Wl[r * WSTR + kk]) =
            *reinterpret_cast<const uint4*>(&g_Whh_lo[(size_t)(n0 + r) * HH + kk]);
    }
    __syncthreads();

    float c_reg[4];
#pragma unroll
    for (int e = 0; e < 4; e++) c_reg[e] = 0.f;

    for (int t = 0; t < TT; t++) {
        const int rb = t & 1;
        const int wb = (t + 1) & 1;

        float4 xg[4];
#pragma unroll
        for (int e = 0; e < 4; e++) {
            int p  = tid + e * 256;
            int bl = p >> 4, u = p & 15;
            xg[e] = *reinterpret_cast<const float4*>(
                &g_xgates[((size_t)t * BB + m0 + bl) * G4 + n0 + (u << 2)]);
        }

        wmma::fragment<wmma::accumulator, 16, 16, 16, float> acc[2];
#pragma unroll
        for (int i = 0; i < 2; i++) wmma::fill_fragment(acc[i], 0.f);

        if (t > 0) {
            const __nv_bfloat16* srcH = g_hb_hi[rb];
            const __nv_bfloat16* srcL = g_hb_lo[rb];

            auto stage = [&](int kt, int s) {
                __nv_bfloat16* Ah = Ab + s * A_STAGE_ELEMS;
                __nv_bfloat16* Al = Ah + 64 * SA;
                int k0 = kt * 64;
#pragma unroll
                for (int i = 0; i < 2; i++) {
                    int chunk = tid + i * 256;
                    int row = chunk >> 3, kk = (chunk & 7) << 3;
                    cp16(&Ah[row * SA + kk], &srcH[(size_t)(m0 + row) * HH + k0 + kk]);
                    cp16(&Al[row * SA + kk], &srcL[(size_t)(m0 + row) * HH + k0 + kk]);
                }
                CP_COMMIT();
            };

            stage(0, 0);
            stage(1, 1);

            for (int kt = 0; kt < NKT; kt++) {
                if (kt < NKT - 1) { CP_WAIT(1); } else { CP_WAIT(0); }
                __syncthreads();
                if (kt + 2 < NKT) stage(kt + 2, (kt + 2) % 3);

                const __nv_bfloat16* Ah = Ab + (kt % 3) * A_STAGE_ELEMS;
                const __nv_bfloat16* Al = Ah + 64 * SA;
                const int k0 = kt * 64;
#pragma unroll
                for (int ks = 0; ks < 64; ks += 16) {
                    wmma::fragment<wmma::matrix_a, 16, 16, 16, __nv_bfloat16, wmma::row_major> ah[2], al[2];
                    wmma::fragment<wmma::matrix_b, 16, 16, 16, __nv_bfloat16, wmma::col_major> bh, bl;
#pragma unroll
                    for (int i = 0; i < 2; i++) {
                        wmma::load_matrix_sync(ah[i], &Ah[(wr * 32 + i * 16) * SA + ks], SA);
                        wmma::load_matrix_sync(al[i], &Al[(wr * 32 + i * 16) * SA + ks], SA);
                    }
                    wmma::load_matrix_sync(bh, &Wh[(wc * 16) * WSTR + k0 + ks], WSTR);
                    wmma::load_matrix_sync(bl, &Wl[(wc * 16) * WSTR + k0 + ks], WSTR);

                    wmma::mma_sync(acc[0], ah[0], bh, acc[0]);
                    wmma::mma_sync(acc[1], ah[1], bh, acc[1]);
                    wmma::mma_sync(acc[0], ah[0], bl, acc[0]);
                    wmma::mma_sync(acc[1], ah[1], bl, acc[1]);
                    wmma::mma_sync(acc[0], al[0], bh, acc[0]);
                    wmma::mma_sync(acc[1], al[1], bh, acc[1]);
                }
            }
            __syncthreads();
        }

#pragma unroll
        for (int i = 0; i < 2; i++)
            wmma::store_matrix_sync(&Cs[(wr * 32 + i * 16) * 64 + wc * 16],
                                    acc[i], 64, wmma::mem_row_major);
        __syncthreads();

#pragma unroll
        for (int e = 0; e < 4; e++) {
            int p  = tid + e * 256;
            int bl = p >> 4, u = p & 15;
            int b  = m0 + bl;
            int j  = (n0 >> 2) + u;

            float4 rec = *reinterpret_cast<float4*>(&Cs[bl * 64 + (u << 2)]);

            float ig = rec.x + xg[e].x;
            float fg = rec.y + xg[e].y;
            float gg = rec.z + xg[e].z;
            float og = rec.w + xg[e].w;

            float c  = c_reg[e];
            float cn = sigf(fg) * c + sigf(ig) * tanhf(gg);
            float hn = sigf(og) * tanhf(cn);

            int sidx = b * HH + j;
            lstm_out[(size_t)t * BH + sidx] = hn;

            if (t + 1 < TT) {
                float keep = 1.f - (float)dones[(t + 1) * BB + b];
                hn *= keep;
                cn *= keep;
                hidden_out[(size_t)(t + 1) * 2 * BH + sidx]      = hn;
                hidden_out[(size_t)(t + 1) * 2 * BH + BH + sidx] = cn;
            }
            c_reg[e] = cn;

            __nv_bfloat16 hi, lo;
            split_bf16(hn, hi, lo);
            g_hb_hi[wb][sidx] = hi;
            g_hb_lo[wb][sidx] = lo;
        }

        __syncthreads();
        if (tid == 0) {
            __threadfence();
            unsigned prev = atomicAdd((unsigned*)&g_bar_cnt[grp], 1);
            if (prev == 31) {
                g_bar_cnt[grp] = 0;
                __threadfence();
                atomicAdd((unsigned*)&g_bar_gen[grp], 1);
            } else {
                unsigned target = (unsigned)(t + 1);
                while (g_bar_gen[grp] < target) { __nanosleep(60); }
            }
        }
        __syncthreads();
    }
}

// ---------------------------------------------------------------
extern "C" void kernel_launch(void* const* d_in, const int* in_sizes, int n_in,
                              void* d_out, int out_size)
{
    const float* x     = (const float*)d_in[0];   // [T,B,IN]
    const int*   dones = (const int*)  d_in[1];   // [T,B]
    const float* W_ih  = (const float*)d_in[2];   // [4H,IN]
    const float* W_hh  = (const float*)d_in[3];   // [4H,H]
    const float* b_ih  = (const float*)d_in[4];   // [4H]
    const float* b_hh  = (const float*)d_in[5];   // [4H]

    float* out        = (float*)d_out;
    float* lstm_out   = out;                       // [T,B,H]
    float* hidden_out = out + (size_t)TT * BH;     // [T,2,B,H]

    cudaFuncSetAttribute(scan_kernel, cudaFuncAttributeMaxDynamicSharedMemorySize, SC_SMEM);
    cudaFuncSetAttribute(xgemm_kernel, cudaFuncAttributeMaxDynamicSharedMemorySize, XG_SMEM);

    // 0) weight reorder + bf16 split + bias merge; x split
    reorder_kernel<<<(G4 * IND) / 256, 256>>>(W_ih, W_hh, b_ih, b_hh);
    splitx_kernel<<<((size_t)MROWS * IND / 4) / 256, 256>>>(x);

    // 1) zero h buffers, barrier state, hidden_out[0]
    init_kernel<<<(2 * BH) / 256, 256>>>(hidden_out);

    // 2) time-parallel input GEMM (bf16x3 wmma, cp.async pipelined)
    {
        dim3 grid(G4 / 64, MROWS / 128);   // (32, 512); x-fastest shares m-tile in L2
        xgemm_kernel<<<grid, 256, XG_SMEM>>>();
    }

    // 3) persistent fused recurrent scan (all 256 steps in one launch)
    {
        dim3 grid(G4 / 64, BB / 64);       // (32, 4) = 128 CTAs, 1 per SM
        scan_kernel<<<grid, 256, SC_SMEM>>>(dones, lstm_out, hidden_out);
    }
}